// round 15
// baseline (speedup 1.0000x reference)
#include <cuda_runtime.h>
#include <math.h>

#define NBATCH 256
#define LSRC   400
#define LATD   32
#define NT     38400
#define NA     38400
#define NBD    76800
#define NROWS  (NT + NA + NBD)

#define SRC_P   36
#define SRCT_P  404

typedef unsigned long long u64;

// ---------------- low-level helpers ----------------
__device__ __forceinline__ void ffma2(u64& acc, u64 a, u64 b) {
    asm("fma.rn.f32x2 %0, %1, %2, %0;" : "+l"(acc) : "l"(a), "l"(b));
}
__device__ __forceinline__ float hadd2(u64 p) {
    float2 f = *reinterpret_cast<float2*>(&p);
    return f.x + f.y;
}
__device__ __forceinline__ void cp_async16(void* smem_dst, const void* gsrc) {
    unsigned s = (unsigned)__cvta_generic_to_shared(smem_dst);
    asm volatile("cp.async.cg.shared.global [%0], [%1], 16;" :: "r"(s), "l"(gsrc));
}
__device__ __forceinline__ void cp_commit() {
    asm volatile("cp.async.commit_group;" ::: "memory");
}
template <int N>
__device__ __forceinline__ void cp_wait() {
    asm volatile("cp.async.wait_group %0;" :: "n"(N) : "memory");
}
__device__ __forceinline__ unsigned to_tf32_bits(float x) {
    unsigned u;
    asm("cvt.rna.tf32.f32 %0, %1;" : "=r"(u) : "f"(x));
    return u;
}
// warp-level tf32 MMA (sm_80+ feature, compiles for plain sm_103)
__device__ __forceinline__ void mma_tf32(float* c, const unsigned* a, unsigned b0, unsigned b1) {
    asm volatile(
        "mma.sync.aligned.m16n8k8.row.col.f32.tf32.tf32.f32 "
        "{%0,%1,%2,%3}, {%4,%5,%6,%7}, {%8,%9}, {%0,%1,%2,%3};"
        : "+f"(c[0]), "+f"(c[1]), "+f"(c[2]), "+f"(c[3])
        : "r"(a[0]), "r"(a[1]), "r"(a[2]), "r"(a[3]), "r"(b0), "r"(b1));
}

// ---------------- scratch (no allocs allowed) ----------------
__device__ __align__(16) float g_q[(size_t)NROWS * LATD];
__device__ __align__(16) float g_cxt[(size_t)NROWS * LATD];
__device__ __align__(16) float g_w1s[966656];   // w1 hi/lo pre-split (3 heads)
__device__ int          g_order[NROWS];
__device__ int          g_hist[3 * 256];
__device__ int          g_cursor[3 * 256];
__device__ int          g_off[3 * 257];
__device__ double       g_loss[3];
__device__ unsigned int g_corr[3];

// ---------------- setup / sort ----------------
__global__ void zero_kernel() {
    int t = blockIdx.x * blockDim.x + threadIdx.x;
    if (t < 3 * 256) { g_hist[t] = 0; g_cursor[t] = 0; }
    if (t < 3) { g_loss[t] = 0.0; g_corr[t] = 0u; }
}

__global__ void __launch_bounds__(256) hist3_kernel(const int* __restrict__ ti,
                                                    const int* __restrict__ ai,
                                                    const int* __restrict__ bi) {
    __shared__ int sh[3 * 256];
    int t = threadIdx.x;
    for (int p = t; p < 3 * 256; p += 256) sh[p] = 0;
    __syncthreads();
    int stride = gridDim.x * blockDim.x;
    for (int i = blockIdx.x * blockDim.x + t; i < NBD; i += stride) {
        if (i < NT)  atomicAdd(&sh[0 * 256 + ti[i]], 1);
        if (i < NA)  atomicAdd(&sh[1 * 256 + ai[i]], 1);
        atomicAdd(&sh[2 * 256 + bi[i]], 1);
    }
    __syncthreads();
    for (int p = t; p < 3 * 256; p += 256) {
        int v = sh[p];
        if (v) atomicAdd(&g_hist[p], v);
    }
}

__global__ void scan_kernel() {
    int head = blockIdx.x;
    int t = threadIdx.x;
    __shared__ int s[256];
    int h = g_hist[head * 256 + t];
    s[t] = h;
    __syncthreads();
    for (int o = 1; o < 256; o <<= 1) {
        int v = (t >= o) ? s[t - o] : 0;
        __syncthreads();
        s[t] += v;
        __syncthreads();
    }
    int excl = s[t] - h;
    g_off[head * 257 + t] = excl;
    g_cursor[head * 256 + t] = excl;
    if (t == 255) g_off[head * 257 + 256] = s[255];
}

__global__ void scatter3_kernel(const int* __restrict__ ti, const int* __restrict__ ai,
                                const int* __restrict__ bi) {
    int i = blockIdx.x * blockDim.x + threadIdx.x;
    if (i < NT) {
        int b = ti[i];
        int pos = atomicAdd(&g_cursor[0 * 256 + b], 1);
        g_order[pos] = i;
    }
    if (i < NA) {
        int b = ai[i];
        int pos = atomicAdd(&g_cursor[1 * 256 + b], 1);
        g_order[NT + pos] = i;
    }
    if (i < NBD) {
        int b = bi[i];
        int pos = atomicAdd(&g_cursor[2 * 256 + b], 1);
        g_order[NT + NA + pos] = i;
    }
}

// ---------------- w1 split: fp32 -> tf32 hi/lo planes ----------------
__global__ void w1split_kernel(const float* __restrict__ w1, int K, int nch, int outoff) {
    int fid = blockIdx.x * blockDim.x + threadIdx.x;
    if (fid >= nch * 2048) return;
    int ch = fid >> 11;
    int rem = fid & 2047;
    int r = rem >> 3, q = rem & 7;
    float4 v = *(const float4*)&w1[(size_t)r * K + ch * 32 + 4 * q];
    float4 h, l;
    h.x = __uint_as_float(to_tf32_bits(v.x)); l.x = v.x - h.x;
    h.y = __uint_as_float(to_tf32_bits(v.y)); l.y = v.y - h.y;
    h.z = __uint_as_float(to_tf32_bits(v.z)); l.z = v.z - h.z;
    h.w = __uint_as_float(to_tf32_bits(v.w)); l.w = v.w - h.w;
    l.x = __uint_as_float(to_tf32_bits(l.x));
    l.y = __uint_as_float(to_tf32_bits(l.y));
    l.z = __uint_as_float(to_tf32_bits(l.z));
    l.w = __uint_as_float(to_tf32_bits(l.w));
    float* dst = g_w1s + outoff + (size_t)ch * 16384;
    *(float4*)&dst[r * 32 + 4 * q] = h;
    *(float4*)&dst[8192 + r * 32 + 4 * q] = l;
}

// ---------------- q projection: 3-stage cp.async ring, FFMA2 ----------------
#define QP_BUF 3200
template <int D>
__global__ void __launch_bounds__(256) qproj_kernel(const float* __restrict__ vecs,
                                                    const float* __restrict__ Aw,
                                                    const float* __restrict__ Ab,
                                                    int rowbase) {
    __shared__ __align__(16) float sm[3 * QP_BUF];
    int t = threadIdx.x;
    int row0 = blockIdx.x * 64;
    int col = t & 31;
    int rbase = (t >> 5) * 8;
    u64 acc[8];
#pragma unroll
    for (int r = 0; r < 8; r++) acc[r] = 0ull;

    constexpr int NC = D / 32;

    auto load_tile = [&](int buf, int k0) {
        float* A_s = sm + buf * QP_BUF;
        float* W_s = A_s + 2048;
#pragma unroll
        for (int it = 0; it < 2; it++) {
            int m = t + 256 * it;
            int r = m >> 3, kq = m & 7;
            cp_async16(&A_s[r * 32 + 4 * kq],
                       &vecs[(size_t)(row0 + r) * D + k0 + 4 * kq]);
        }
        {
            int c = t >> 3, kq = t & 7;
            cp_async16(&W_s[c * 36 + 4 * kq],
                       &Aw[(size_t)c * D + k0 + 4 * kq]);
        }
        cp_commit();
    };

    load_tile(0, 0);
    load_tile(1, 32);
    for (int c = 0; c < NC; c++) {
        if (c == NC - 1) cp_wait<0>(); else cp_wait<1>();
        __syncthreads();
        if (c + 2 < NC) load_tile((c + 2) % 3, (c + 2) * 32);
        const float* A_s = sm + (c % 3) * QP_BUF;
        const float* W_s = A_s + 2048;
#pragma unroll
        for (int kq = 0; kq < 8; kq++) {
            ulonglong2 w4 = *(const ulonglong2*)&W_s[col * 36 + 4 * kq];
#pragma unroll
            for (int r = 0; r < 8; r++) {
                ulonglong2 a4 = *(const ulonglong2*)&A_s[(rbase + r) * 32 + 4 * kq];
                ffma2(acc[r], a4.x, w4.x);
                ffma2(acc[r], a4.y, w4.y);
            }
        }
    }
    float bias = Ab[col];
#pragma unroll
    for (int r = 0; r < 8; r++)
        g_q[(size_t)(rowbase + row0 + rbase + r) * LATD + col] = hadd2(acc[r]) + bias;
}

// ---------------- attention: 8 rows/warp/pass, no max-subtraction ----------------
__global__ void __launch_bounds__(256) attn_kernel(const float* __restrict__ src) {
    extern __shared__ __align__(16) float smem[];
    float* src_s = smem;
    float* srcT  = smem + LSRC * SRC_P;
    float* att_s = srcT + LATD * SRCT_P;

    int t = threadIdx.x;
    int b = blockIdx.x;
    int head = blockIdx.y;
    int rowbase = (head == 0) ? 0 : ((head == 1) ? NT : (NT + NA));

    for (int m = t; m < LSRC * LATD; m += 256) {
        float v = src[(size_t)b * (LSRC * LATD) + m];
        int l = m >> 5, d = m & 31;
        src_s[l * SRC_P + d] = v;
        srcT[d * SRCT_P + l] = v;
    }
    __syncthreads();

    int w = t >> 5, j = t & 31;
    int start = g_off[head * 257 + b];
    int end   = g_off[head * 257 + b + 1];

    for (int r0 = start + w * 8; r0 < end; r0 += 64) {
        int nr = end - r0; if (nr > 8) nr = 8;

#pragma unroll
        for (int pp = 0; pp < 8; pp += 2) {
            if (pp >= nr) break;
            int i0 = g_order[rowbase + r0 + pp];
            int i1 = (pp + 1 < nr) ? g_order[rowbase + r0 + pp + 1] : i0;
            u64 q0p[16], q1p[16];
            const ulonglong2* p0 = (const ulonglong2*)&g_q[(size_t)(rowbase + i0) * LATD];
            const ulonglong2* p1 = (const ulonglong2*)&g_q[(size_t)(rowbase + i1) * LATD];
#pragma unroll
            for (int m = 0; m < 8; m++) {
                ulonglong2 v0 = p0[m]; q0p[2 * m] = v0.x; q0p[2 * m + 1] = v0.y;
                ulonglong2 v1 = p1[m]; q1p[2 * m] = v1.x; q1p[2 * m + 1] = v1.y;
            }
            float ev0[13], ev1[13];
            float ss0 = 0.f, ss1 = 0.f;
#pragma unroll
            for (int tt = 0; tt < 13; tt++) {
                int l = 32 * tt + j;
                float e0 = 0.f, e1 = 0.f;
                if (l < LSRC) {
                    const ulonglong2* sp = (const ulonglong2*)&src_s[l * SRC_P];
                    u64 s0p = 0ull, s1p = 0ull;
#pragma unroll
                    for (int kq = 0; kq < 8; kq++) {
                        ulonglong2 sr = sp[kq];
                        ffma2(s0p, sr.x, q0p[2 * kq]); ffma2(s0p, sr.y, q0p[2 * kq + 1]);
                        ffma2(s1p, sr.x, q1p[2 * kq]); ffma2(s1p, sr.y, q1p[2 * kq + 1]);
                    }
                    e0 = __expf(hadd2(s0p));
                    e1 = __expf(hadd2(s1p));
                }
                ev0[tt] = e0; ev1[tt] = e1;
                ss0 += e0; ss1 += e1;
            }
#pragma unroll
            for (int o = 16; o > 0; o >>= 1) {
                ss0 += __shfl_xor_sync(0xffffffffu, ss0, o);
                ss1 += __shfl_xor_sync(0xffffffffu, ss1, o);
            }
            float inv0 = 1.f / ss0, inv1 = 1.f / ss1;
            float* a0 = &att_s[(w * 8 + pp) * LSRC];
            float* a1 = &att_s[(w * 8 + pp + 1) * LSRC];
#pragma unroll
            for (int tt = 0; tt < 13; tt++) {
                int l = 32 * tt + j;
                if (l < LSRC) { a0[l] = ev0[tt] * inv0; a1[l] = ev1[tt] * inv1; }
            }
        }
        __syncwarp();

        u64 cp[8];
#pragma unroll
        for (int rr = 0; rr < 8; rr++) cp[rr] = 0ull;
        const ulonglong2* vt = (const ulonglong2*)&srcT[j * SRCT_P];
#pragma unroll 2
        for (int lq = 0; lq < LSRC / 4; lq++) {
            ulonglong2 v = vt[lq];
#pragma unroll
            for (int rr = 0; rr < 8; rr++) {
                ulonglong2 x = ((const ulonglong2*)&att_s[(w * 8 + rr) * LSRC])[lq];
                ffma2(cp[rr], x.x, v.x);
                ffma2(cp[rr], x.y, v.y);
            }
        }
        for (int rr = 0; rr < nr; rr++) {
            int i = g_order[rowbase + r0 + rr];
            g_cxt[(size_t)(rowbase + i) * LATD + j] = hadd2(cp[rr]);
        }
        __syncwarp();
    }
}

// ---------------- fused MLP: mma.sync 3xTF32 MLP1 + FFMA2 MLP2 + loss ----------------
// tile 64 rows x 256 hidden; warp tile = 64 rows x 32 cols (minimal smem traffic)
// buffer: A 64*36=2304 | Bhi 256*32=8192 (XOR-f4 swizzled) | Blo 8192 -> 18688/buf
#define MLP_BUF 18688
#define MLP_SMEM_FLOATS (2 * MLP_BUF)
#define HP 264
template <int D, int C, bool BCE>
__global__ void __launch_bounds__(256) mlp_kernel(const float* __restrict__ vecs,
                                                  int w1s_off,
                                                  const float* __restrict__ b1,
                                                  const float* __restrict__ w2,
                                                  const float* __restrict__ b2,
                                                  const int* __restrict__ labels,
                                                  int rowbase, int head) {
    constexpr int K = D + LATD;
    constexpr int NC = K / 32;
    extern __shared__ __align__(16) float sm[];
    float* h_s     = sm;                 // epilogue aliases
    float* logit_s = sm + 64 * HP;
    float* red     = logit_s + 64 * C;

    int t = threadIdx.x;
    int row0 = blockIdx.x * 64;
    int wid = t >> 5, lane = t & 31;
    int cb = wid * 32;       // this warp's 32-col group
    int g = lane >> 2, tq = lane & 3;

    float acc[16][4];        // [rt*4+nt][4]: 4 row-tiles (m16) x 4 n-tiles (n8)
#pragma unroll
    for (int q = 0; q < 16; q++)
#pragma unroll
        for (int x = 0; x < 4; x++) acc[q][x] = 0.f;

    const float* cxt = g_cxt + (size_t)rowbase * LATD;
    const float* w1s = g_w1s + w1s_off;

    auto load_tile = [&](int buf, int c) {
        int k0 = c * 32;
        float* A_s  = sm + buf * MLP_BUF;
        float* Bh_s = A_s + 2304;
        float* Bl_s = Bh_s + 8192;
        if (k0 < D) {
#pragma unroll
            for (int it = 0; it < 2; it++) {
                int m = t + 256 * it;
                int r = m >> 3, kq = m & 7;
                cp_async16(&A_s[r * 36 + 4 * kq],
                           &vecs[(size_t)(row0 + r) * D + k0 + 4 * kq]);
            }
        } else {
#pragma unroll
            for (int it = 0; it < 2; it++) {
                int m = t + 256 * it;
                int r = m >> 3, kq = m & 7;
                cp_async16(&A_s[r * 36 + 4 * kq],
                           &cxt[(size_t)(row0 + r) * LATD + 4 * kq]);
            }
        }
        // B planes at 32-float pitch with XOR-f4 swizzle: f4' = f4 ^ (row&7)
        const float* bh = w1s + (size_t)c * 16384;
#pragma unroll
        for (int it = 0; it < 8; it++) {
            int m = t + 256 * it;
            int r = m >> 3, q = m & 7;
            int sq = q ^ (r & 7);
            cp_async16(&Bh_s[r * 32 + 4 * sq], &bh[r * 32 + 4 * q]);
            cp_async16(&Bl_s[r * 32 + 4 * sq], &bh[8192 + r * 32 + 4 * q]);
        }
        cp_commit();
    };

    load_tile(0, 0);
    for (int c = 0; c < NC; c++) {
        if (c + 1 < NC) { load_tile((c + 1) & 1, c + 1); cp_wait<1>(); }
        else            { cp_wait<0>(); }
        __syncthreads();
        const float* A_s  = sm + (c & 1) * MLP_BUF;
        const float* Bh_s = A_s + 2304;
        const float* Bl_s = Bh_s + 8192;
#pragma unroll
        for (int ks = 0; ks < 4; ks++) {
            // A fragments for all 4 row-tiles (reused across the 4 n-tiles)
            unsigned ah[4][4], al[4][4];
#pragma unroll
            for (int rt = 0; rt < 4; rt++) {
                int ra = rt * 16 + g;
                float v0 = A_s[ra * 36 + ks * 8 + tq];
                float v1 = A_s[(ra + 8) * 36 + ks * 8 + tq];
                float v2 = A_s[ra * 36 + ks * 8 + tq + 4];
                float v3 = A_s[(ra + 8) * 36 + ks * 8 + tq + 4];
                ah[rt][0] = to_tf32_bits(v0); al[rt][0] = to_tf32_bits(v0 - __uint_as_float(ah[rt][0]));
                ah[rt][1] = to_tf32_bits(v1); al[rt][1] = to_tf32_bits(v1 - __uint_as_float(ah[rt][1]));
                ah[rt][2] = to_tf32_bits(v2); al[rt][2] = to_tf32_bits(v2 - __uint_as_float(ah[rt][2]));
                ah[rt][3] = to_tf32_bits(v3); al[rt][3] = to_tf32_bits(v3 - __uint_as_float(ah[rt][3]));
            }
            // swizzled B float-offsets for this (ks, lane): conflict-free across warp
            int sw0 = (((2 * ks) ^ g) << 2) + tq;
            int sw1 = (((2 * ks + 1) ^ g) << 2) + tq;
#pragma unroll
            for (int nt = 0; nt < 4; nt++) {
                int bbase = (cb + nt * 8 + g) * 32;
                unsigned bh0 = __float_as_uint(Bh_s[bbase + sw0]);
                unsigned bh1 = __float_as_uint(Bh_s[bbase + sw1]);
                unsigned bl0 = __float_as_uint(Bl_s[bbase + sw0]);
                unsigned bl1 = __float_as_uint(Bl_s[bbase + sw1]);
#pragma unroll
                for (int rt = 0; rt < 4; rt++) {
                    mma_tf32(acc[rt * 4 + nt], ah[rt], bh0, bh1);
                    mma_tf32(acc[rt * 4 + nt], ah[rt], bl0, bl1);
                    mma_tf32(acc[rt * 4 + nt], al[rt], bh0, bh1);
                }
            }
        }
        __syncthreads();
    }

    // epilogue: h = relu(D + b1) from accumulator registers -> h_s
#pragma unroll
    for (int nt = 0; nt < 4; nt++) {
        int col = cb + nt * 8 + 2 * tq;
        float bA = b1[col], bB = b1[col + 1];
#pragma unroll
        for (int rt = 0; rt < 4; rt++) {
            int row = rt * 16 + g;
            float* a = acc[rt * 4 + nt];
            h_s[row * HP + col]           = fmaxf(a[0] + bA, 0.f);
            h_s[row * HP + col + 1]       = fmaxf(a[1] + bB, 0.f);
            h_s[(row + 8) * HP + col]     = fmaxf(a[2] + bA, 0.f);
            h_s[(row + 8) * HP + col + 1] = fmaxf(a[3] + bB, 0.f);
        }
    }
    __syncthreads();

    // MLP2: logits = h @ w2^T + b2 (FFMA2)
    for (int p = t; p < 64 * C; p += 256) {
        int r = p / C, cls = p - r * C;
        const ulonglong2* hp = (const ulonglong2*)&h_s[r * HP];
        const ulonglong2* wp = (const ulonglong2*)&w2[(size_t)cls * 256];
        u64 sp2 = 0ull;
#pragma unroll 8
        for (int kq = 0; kq < 64; kq++) {
            ulonglong2 h4 = hp[kq]; ulonglong2 w4 = wp[kq];
            ffma2(sp2, h4.x, w4.x); ffma2(sp2, h4.y, w4.y);
        }
        logit_s[p] = hadd2(sp2) + b2[cls];
    }
    __syncthreads();

    // per-row loss / accuracy
    if (t < 64) {
        int gi = row0 + t;
        int y = labels[gi];
        float loss;
        int corr;
        if (BCE) {
            float z = logit_s[t];
            float sp = (z > 0.f) ? (z + log1pf(__expf(-z))) : log1pf(__expf(z));
            loss = sp - (float)y * z;
            corr = (((z > 0.f) ? 1 : 0) == y) ? 1 : 0;
        } else {
            float mx = logit_s[t * C];
            int am = 0;
#pragma unroll
            for (int c = 1; c < C; c++) {
                float v = logit_s[t * C + c];
                if (v > mx) { mx = v; am = c; }
            }
            float s = 0.f;
#pragma unroll
            for (int c = 0; c < C; c++) s += __expf(logit_s[t * C + c] - mx);
            loss = logf(s) + mx - logit_s[t * C + y];
            corr = (am == y) ? 1 : 0;
        }
        red[t] = loss;
        ((int*)red)[64 + t] = corr;
    }
    __syncthreads();
    if (t < 32) {
        float L = red[t] + red[t + 32];
        int Ck = ((int*)red)[64 + t] + ((int*)red)[64 + t + 32];
#pragma unroll
        for (int o = 16; o > 0; o >>= 1) {
            L += __shfl_xor_sync(0xffffffffu, L, o);
            Ck += __shfl_xor_sync(0xffffffffu, Ck, o);
        }
        if (t == 0) {
            atomicAdd(&g_loss[head], (double)L);
            atomicAdd(&g_corr[head], (unsigned int)Ck);
        }
    }
}

__global__ void finalize_kernel(float* __restrict__ out) {
    if (threadIdx.x == 0 && blockIdx.x == 0) {
        double L = g_loss[0] + g_loss[1] + g_loss[2];
        out[0] = (float)(L / (double)NBATCH);
        out[1] = (float)g_corr[1] / (float)NA;
        out[2] = (float)g_corr[0] / (float)NT;
        out[3] = (float)g_corr[2] / (float)NBD;
    }
}

// ---------------- launch (fork/join stream graph) ----------------
extern "C" void kernel_launch(void* const* d_in, const int* in_sizes, int n_in,
                              void* d_out, int out_size) {
    const float* src        = (const float*)d_in[0];
    const float* topo_vecs  = (const float*)d_in[1];
    const float* atom_vecs  = (const float*)d_in[2];
    const float* bond_vecs  = (const float*)d_in[3];
    const int*   topo_idx   = (const int*)d_in[4];
    const int*   atom_idx   = (const int*)d_in[5];
    const int*   bond_idx   = (const int*)d_in[6];
    const int*   topo_lab   = (const int*)d_in[7];
    const int*   atom_lab   = (const int*)d_in[8];
    const int*   bond_lab   = (const int*)d_in[9];
    const float* A_topo_w   = (const float*)d_in[10];
    const float* A_topo_b   = (const float*)d_in[11];
    const float* A_atom_w   = (const float*)d_in[12];
    const float* A_atom_b   = (const float*)d_in[13];
    const float* A_bond_w   = (const float*)d_in[14];
    const float* A_bond_b   = (const float*)d_in[15];
    const float* topo_w1    = (const float*)d_in[16];
    const float* topo_b1    = (const float*)d_in[17];
    const float* topo_w2    = (const float*)d_in[18];
    const float* topo_b2    = (const float*)d_in[19];
    const float* atom_w1    = (const float*)d_in[20];
    const float* atom_b1    = (const float*)d_in[21];
    const float* atom_w2    = (const float*)d_in[22];
    const float* atom_b2    = (const float*)d_in[23];
    const float* bond_w1    = (const float*)d_in[24];
    const float* bond_b1    = (const float*)d_in[25];
    const float* bond_w2    = (const float*)d_in[26];
    const float* bond_b2    = (const float*)d_in[27];
    float* out = (float*)d_out;

    int attn_smem = (LSRC * SRC_P + LATD * SRCT_P + 64 * LSRC) * (int)sizeof(float);
    int mlp_smem  = MLP_SMEM_FLOATS * (int)sizeof(float);

    static cudaStream_t sA = nullptr, sB = nullptr;
    static cudaEvent_t eRoot, eSort, eAttn, eW, eT, eA2;
    if (!sA) {
        cudaStreamCreateWithFlags(&sA, cudaStreamNonBlocking);
        cudaStreamCreateWithFlags(&sB, cudaStreamNonBlocking);
        cudaEventCreateWithFlags(&eRoot, cudaEventDisableTiming);
        cudaEventCreateWithFlags(&eSort, cudaEventDisableTiming);
        cudaEventCreateWithFlags(&eAttn, cudaEventDisableTiming);
        cudaEventCreateWithFlags(&eW,    cudaEventDisableTiming);
        cudaEventCreateWithFlags(&eT,    cudaEventDisableTiming);
        cudaEventCreateWithFlags(&eA2,   cudaEventDisableTiming);
        cudaFuncSetAttribute(attn_kernel, cudaFuncAttributeMaxDynamicSharedMemorySize, attn_smem);
        cudaFuncSetAttribute(mlp_kernel<512, 1, true>,   cudaFuncAttributeMaxDynamicSharedMemorySize, mlp_smem);
        cudaFuncSetAttribute(mlp_kernel<512, 40, false>, cudaFuncAttributeMaxDynamicSharedMemorySize, mlp_smem);
        cudaFuncSetAttribute(mlp_kernel<768, 4, false>,  cudaFuncAttributeMaxDynamicSharedMemorySize, mlp_smem);
    }

    cudaEventRecord(eRoot, 0);
    cudaStreamWaitEvent(sA, eRoot, 0);
    cudaStreamWaitEvent(sB, eRoot, 0);

    // sort chain on sA
    zero_kernel<<<4, 256, 0, sA>>>();
    hist3_kernel<<<64, 256, 0, sA>>>(topo_idx, atom_idx, bond_idx);
    scan_kernel<<<3, 256, 0, sA>>>();
    scatter3_kernel<<<(NBD + 255) / 256, 256, 0, sA>>>(topo_idx, atom_idx, bond_idx);
    cudaEventRecord(eSort, sA);

    // w1 hi/lo pre-split on sB
    w1split_kernel<<<(17 * 2048 + 255) / 256, 256, 0, sB>>>(topo_w1, 544, 17, 0);
    w1split_kernel<<<(17 * 2048 + 255) / 256, 256, 0, sB>>>(atom_w1, 544, 17, 278528);
    w1split_kernel<<<(25 * 2048 + 255) / 256, 256, 0, sB>>>(bond_w1, 800, 25, 557056);
    cudaEventRecord(eW, sB);

    // qproj on default stream
    qproj_kernel<512><<<NT / 64, 256>>>(topo_vecs, A_topo_w, A_topo_b, 0);
    qproj_kernel<512><<<NA / 64, 256>>>(atom_vecs, A_atom_w, A_atom_b, NT);
    qproj_kernel<768><<<NBD / 64, 256>>>(bond_vecs, A_bond_w, A_bond_b, NT + NA);

    cudaStreamWaitEvent(0, eSort, 0);
    attn_kernel<<<dim3(256, 3), 256, attn_smem>>>(src);
    cudaEventRecord(eAttn, 0);

    // three MLP heads concurrent (need attn + w1 split)
    cudaStreamWaitEvent(sA, eAttn, 0);
    cudaStreamWaitEvent(sA, eW, 0);
    cudaStreamWaitEvent(sB, eAttn, 0);
    cudaStreamWaitEvent(0, eW, 0);
    mlp_kernel<512, 1, true><<<NT / 64, 256, mlp_smem, sA>>>(
        topo_vecs, 0, topo_b1, topo_w2, topo_b2, topo_lab, 0, 0);
    mlp_kernel<512, 40, false><<<NA / 64, 256, mlp_smem, sB>>>(
        atom_vecs, 278528, atom_b1, atom_w2, atom_b2, atom_lab, NT, 1);
    mlp_kernel<768, 4, false><<<NBD / 64, 256, mlp_smem>>>(
        bond_vecs, 557056, bond_b1, bond_w2, bond_b2, bond_lab, NT + NA, 2);
    cudaEventRecord(eT, sA);
    cudaEventRecord(eA2, sB);
    cudaStreamWaitEvent(0, eT, 0);
    cudaStreamWaitEvent(0, eA2, 0);

    finalize_kernel<<<1, 1>>>(out);
}

// round 16
// speedup vs baseline: 1.5917x; 1.5917x over previous
#include <cuda_runtime.h>
#include <math.h>

#define NBATCH 256
#define LSRC   400
#define LATD   32
#define NT     38400
#define NA     38400
#define NBD    76800
#define NROWS  (NT + NA + NBD)

#define SRC_P   36
#define SRCT_P  404

typedef unsigned long long u64;

// ---------------- low-level helpers ----------------
__device__ __forceinline__ void ffma2(u64& acc, u64 a, u64 b) {
    asm("fma.rn.f32x2 %0, %1, %2, %0;" : "+l"(acc) : "l"(a), "l"(b));
}
__device__ __forceinline__ float hadd2(u64 p) {
    float2 f = *reinterpret_cast<float2*>(&p);
    return f.x + f.y;
}
__device__ __forceinline__ void cp_async16(void* smem_dst, const void* gsrc) {
    unsigned s = (unsigned)__cvta_generic_to_shared(smem_dst);
    asm volatile("cp.async.cg.shared.global [%0], [%1], 16;" :: "r"(s), "l"(gsrc));
}
__device__ __forceinline__ void cp_commit() {
    asm volatile("cp.async.commit_group;" ::: "memory");
}
template <int N>
__device__ __forceinline__ void cp_wait() {
    asm volatile("cp.async.wait_group %0;" :: "n"(N) : "memory");
}
__device__ __forceinline__ unsigned to_tf32_bits(float x) {
    unsigned u;
    asm("cvt.rna.tf32.f32 %0, %1;" : "=r"(u) : "f"(x));
    return u;
}
// warp-level tf32 MMA (sm_80+ feature, compiles for plain sm_103)
__device__ __forceinline__ void mma_tf32(float* c, const unsigned* a, unsigned b0, unsigned b1) {
    asm volatile(
        "mma.sync.aligned.m16n8k8.row.col.f32.tf32.tf32.f32 "
        "{%0,%1,%2,%3}, {%4,%5,%6,%7}, {%8,%9}, {%0,%1,%2,%3};"
        : "+f"(c[0]), "+f"(c[1]), "+f"(c[2]), "+f"(c[3])
        : "r"(a[0]), "r"(a[1]), "r"(a[2]), "r"(a[3]), "r"(b0), "r"(b1));
}

// ---------------- scratch (no allocs allowed) ----------------
__device__ __align__(16) float g_q[(size_t)NROWS * LATD];
__device__ __align__(16) float g_cxt[(size_t)NROWS * LATD];
__device__ __align__(16) float g_w1s[966656];   // w1 hi/lo pre-split (3 heads)
__device__ int          g_order[NROWS];
__device__ int          g_hist[3 * 256];
__device__ int          g_cursor[3 * 256];
__device__ int          g_off[3 * 257];
__device__ double       g_loss[3];
__device__ unsigned int g_corr[3];

// ---------------- setup / sort ----------------
__global__ void zero_kernel() {
    int t = blockIdx.x * blockDim.x + threadIdx.x;
    if (t < 3 * 256) { g_hist[t] = 0; g_cursor[t] = 0; }
    if (t < 3) { g_loss[t] = 0.0; g_corr[t] = 0u; }
}

__global__ void __launch_bounds__(256) hist3_kernel(const int* __restrict__ ti,
                                                    const int* __restrict__ ai,
                                                    const int* __restrict__ bi) {
    __shared__ int sh[3 * 256];
    int t = threadIdx.x;
    for (int p = t; p < 3 * 256; p += 256) sh[p] = 0;
    __syncthreads();
    int stride = gridDim.x * blockDim.x;
    for (int i = blockIdx.x * blockDim.x + t; i < NBD; i += stride) {
        if (i < NT)  atomicAdd(&sh[0 * 256 + ti[i]], 1);
        if (i < NA)  atomicAdd(&sh[1 * 256 + ai[i]], 1);
        atomicAdd(&sh[2 * 256 + bi[i]], 1);
    }
    __syncthreads();
    for (int p = t; p < 3 * 256; p += 256) {
        int v = sh[p];
        if (v) atomicAdd(&g_hist[p], v);
    }
}

__global__ void scan_kernel() {
    int head = blockIdx.x;
    int t = threadIdx.x;
    __shared__ int s[256];
    int h = g_hist[head * 256 + t];
    s[t] = h;
    __syncthreads();
    for (int o = 1; o < 256; o <<= 1) {
        int v = (t >= o) ? s[t - o] : 0;
        __syncthreads();
        s[t] += v;
        __syncthreads();
    }
    int excl = s[t] - h;
    g_off[head * 257 + t] = excl;
    g_cursor[head * 256 + t] = excl;
    if (t == 255) g_off[head * 257 + 256] = s[255];
}

__global__ void scatter3_kernel(const int* __restrict__ ti, const int* __restrict__ ai,
                                const int* __restrict__ bi) {
    int i = blockIdx.x * blockDim.x + threadIdx.x;
    if (i < NT) {
        int b = ti[i];
        int pos = atomicAdd(&g_cursor[0 * 256 + b], 1);
        g_order[pos] = i;
    }
    if (i < NA) {
        int b = ai[i];
        int pos = atomicAdd(&g_cursor[1 * 256 + b], 1);
        g_order[NT + pos] = i;
    }
    if (i < NBD) {
        int b = bi[i];
        int pos = atomicAdd(&g_cursor[2 * 256 + b], 1);
        g_order[NT + NA + pos] = i;
    }
}

// ---------------- w1 split: fp32 -> tf32 hi/lo planes ----------------
__global__ void w1split_kernel(const float* __restrict__ w1, int K, int nch, int outoff) {
    int fid = blockIdx.x * blockDim.x + threadIdx.x;
    if (fid >= nch * 2048) return;
    int ch = fid >> 11;
    int rem = fid & 2047;
    int r = rem >> 3, q = rem & 7;
    float4 v = *(const float4*)&w1[(size_t)r * K + ch * 32 + 4 * q];
    float4 h, l;
    h.x = __uint_as_float(to_tf32_bits(v.x)); l.x = v.x - h.x;
    h.y = __uint_as_float(to_tf32_bits(v.y)); l.y = v.y - h.y;
    h.z = __uint_as_float(to_tf32_bits(v.z)); l.z = v.z - h.z;
    h.w = __uint_as_float(to_tf32_bits(v.w)); l.w = v.w - h.w;
    l.x = __uint_as_float(to_tf32_bits(l.x));
    l.y = __uint_as_float(to_tf32_bits(l.y));
    l.z = __uint_as_float(to_tf32_bits(l.z));
    l.w = __uint_as_float(to_tf32_bits(l.w));
    float* dst = g_w1s + outoff + (size_t)ch * 16384;
    *(float4*)&dst[r * 32 + 4 * q] = h;
    *(float4*)&dst[8192 + r * 32 + 4 * q] = l;
}

// ---------------- q projection: 3-stage cp.async ring, FFMA2 ----------------
#define QP_BUF 3200
template <int D>
__global__ void __launch_bounds__(256) qproj_kernel(const float* __restrict__ vecs,
                                                    const float* __restrict__ Aw,
                                                    const float* __restrict__ Ab,
                                                    int rowbase) {
    __shared__ __align__(16) float sm[3 * QP_BUF];
    int t = threadIdx.x;
    int row0 = blockIdx.x * 64;
    int col = t & 31;
    int rbase = (t >> 5) * 8;
    u64 acc[8];
#pragma unroll
    for (int r = 0; r < 8; r++) acc[r] = 0ull;

    constexpr int NC = D / 32;

    auto load_tile = [&](int buf, int k0) {
        float* A_s = sm + buf * QP_BUF;
        float* W_s = A_s + 2048;
#pragma unroll
        for (int it = 0; it < 2; it++) {
            int m = t + 256 * it;
            int r = m >> 3, kq = m & 7;
            cp_async16(&A_s[r * 32 + 4 * kq],
                       &vecs[(size_t)(row0 + r) * D + k0 + 4 * kq]);
        }
        {
            int c = t >> 3, kq = t & 7;
            cp_async16(&W_s[c * 36 + 4 * kq],
                       &Aw[(size_t)c * D + k0 + 4 * kq]);
        }
        cp_commit();
    };

    load_tile(0, 0);
    load_tile(1, 32);
    for (int c = 0; c < NC; c++) {
        if (c == NC - 1) cp_wait<0>(); else cp_wait<1>();
        __syncthreads();
        if (c + 2 < NC) load_tile((c + 2) % 3, (c + 2) * 32);
        const float* A_s = sm + (c % 3) * QP_BUF;
        const float* W_s = A_s + 2048;
#pragma unroll
        for (int kq = 0; kq < 8; kq++) {
            ulonglong2 w4 = *(const ulonglong2*)&W_s[col * 36 + 4 * kq];
#pragma unroll
            for (int r = 0; r < 8; r++) {
                ulonglong2 a4 = *(const ulonglong2*)&A_s[(rbase + r) * 32 + 4 * kq];
                ffma2(acc[r], a4.x, w4.x);
                ffma2(acc[r], a4.y, w4.y);
            }
        }
    }
    float bias = Ab[col];
#pragma unroll
    for (int r = 0; r < 8; r++)
        g_q[(size_t)(rowbase + row0 + rbase + r) * LATD + col] = hadd2(acc[r]) + bias;
}

// ---------------- attention: 8 rows/warp/pass, no max-subtraction ----------------
__global__ void __launch_bounds__(256) attn_kernel(const float* __restrict__ src) {
    extern __shared__ __align__(16) float smem[];
    float* src_s = smem;
    float* srcT  = smem + LSRC * SRC_P;
    float* att_s = srcT + LATD * SRCT_P;

    int t = threadIdx.x;
    int b = blockIdx.x;
    int head = blockIdx.y;
    int rowbase = (head == 0) ? 0 : ((head == 1) ? NT : (NT + NA));

    for (int m = t; m < LSRC * LATD; m += 256) {
        float v = src[(size_t)b * (LSRC * LATD) + m];
        int l = m >> 5, d = m & 31;
        src_s[l * SRC_P + d] = v;
        srcT[d * SRCT_P + l] = v;
    }
    __syncthreads();

    int w = t >> 5, j = t & 31;
    int start = g_off[head * 257 + b];
    int end   = g_off[head * 257 + b + 1];

    for (int r0 = start + w * 8; r0 < end; r0 += 64) {
        int nr = end - r0; if (nr > 8) nr = 8;

#pragma unroll
        for (int pp = 0; pp < 8; pp += 2) {
            if (pp >= nr) break;
            int i0 = g_order[rowbase + r0 + pp];
            int i1 = (pp + 1 < nr) ? g_order[rowbase + r0 + pp + 1] : i0;
            u64 q0p[16], q1p[16];
            const ulonglong2* p0 = (const ulonglong2*)&g_q[(size_t)(rowbase + i0) * LATD];
            const ulonglong2* p1 = (const ulonglong2*)&g_q[(size_t)(rowbase + i1) * LATD];
#pragma unroll
            for (int m = 0; m < 8; m++) {
                ulonglong2 v0 = p0[m]; q0p[2 * m] = v0.x; q0p[2 * m + 1] = v0.y;
                ulonglong2 v1 = p1[m]; q1p[2 * m] = v1.x; q1p[2 * m + 1] = v1.y;
            }
            float ev0[13], ev1[13];
            float ss0 = 0.f, ss1 = 0.f;
#pragma unroll
            for (int tt = 0; tt < 13; tt++) {
                int l = 32 * tt + j;
                float e0 = 0.f, e1 = 0.f;
                if (l < LSRC) {
                    const ulonglong2* sp = (const ulonglong2*)&src_s[l * SRC_P];
                    u64 s0p = 0ull, s1p = 0ull;
#pragma unroll
                    for (int kq = 0; kq < 8; kq++) {
                        ulonglong2 sr = sp[kq];
                        ffma2(s0p, sr.x, q0p[2 * kq]); ffma2(s0p, sr.y, q0p[2 * kq + 1]);
                        ffma2(s1p, sr.x, q1p[2 * kq]); ffma2(s1p, sr.y, q1p[2 * kq + 1]);
                    }
                    e0 = __expf(hadd2(s0p));
                    e1 = __expf(hadd2(s1p));
                }
                ev0[tt] = e0; ev1[tt] = e1;
                ss0 += e0; ss1 += e1;
            }
#pragma unroll
            for (int o = 16; o > 0; o >>= 1) {
                ss0 += __shfl_xor_sync(0xffffffffu, ss0, o);
                ss1 += __shfl_xor_sync(0xffffffffu, ss1, o);
            }
            float inv0 = 1.f / ss0, inv1 = 1.f / ss1;
            float* a0 = &att_s[(w * 8 + pp) * LSRC];
            float* a1 = &att_s[(w * 8 + pp + 1) * LSRC];
#pragma unroll
            for (int tt = 0; tt < 13; tt++) {
                int l = 32 * tt + j;
                if (l < LSRC) { a0[l] = ev0[tt] * inv0; a1[l] = ev1[tt] * inv1; }
            }
        }
        __syncwarp();

        u64 cp[8];
#pragma unroll
        for (int rr = 0; rr < 8; rr++) cp[rr] = 0ull;
        const ulonglong2* vt = (const ulonglong2*)&srcT[j * SRCT_P];
#pragma unroll 2
        for (int lq = 0; lq < LSRC / 4; lq++) {
            ulonglong2 v = vt[lq];
#pragma unroll
            for (int rr = 0; rr < 8; rr++) {
                ulonglong2 x = ((const ulonglong2*)&att_s[(w * 8 + rr) * LSRC])[lq];
                ffma2(cp[rr], x.x, v.x);
                ffma2(cp[rr], x.y, v.y);
            }
        }
        for (int rr = 0; rr < nr; rr++) {
            int i = g_order[rowbase + r0 + rr];
            g_cxt[(size_t)(rowbase + i) * LATD + j] = hadd2(cp[rr]);
        }
        __syncwarp();
    }
}

// ---------------- fused MLP: mma.sync 3xTF32 MLP1 + FFMA2 MLP2 + loss ----------------
// tile 64 rows x 256 hidden; warp tile = 32 rows x 64 cols
// buffer: A 64*36=2304 | Bhi 256*32=8192 (XOR-f4 swizzled) | Blo 8192 -> 18688/buf
#define MLP_BUF 18688
#define MLP_SMEM_FLOATS (2 * MLP_BUF)
#define HP 264
template <int D, int C, bool BCE>
__global__ void __launch_bounds__(256) mlp_kernel(const float* __restrict__ vecs,
                                                  int w1s_off,
                                                  const float* __restrict__ b1,
                                                  const float* __restrict__ w2,
                                                  const float* __restrict__ b2,
                                                  const int* __restrict__ labels,
                                                  int rowbase, int head) {
    constexpr int K = D + LATD;
    constexpr int NC = K / 32;
    extern __shared__ __align__(16) float sm[];
    float* h_s     = sm;                 // epilogue aliases
    float* logit_s = sm + 64 * HP;
    float* red     = logit_s + 64 * C;

    int t = threadIdx.x;
    int row0 = blockIdx.x * 64;
    int wid = t >> 5, lane = t & 31;
    int wr = wid & 1;        // 32-row group (2 groups)
    int wc = wid >> 1;       // 64-col group (4 groups)
    int g = lane >> 2, tq = lane & 3;

    float acc[16][4];        // [rt*8+nt][4]: 2 row-tiles (m16) x 8 n-tiles (n8)
#pragma unroll
    for (int q = 0; q < 16; q++)
#pragma unroll
        for (int x = 0; x < 4; x++) acc[q][x] = 0.f;

    const float* cxt = g_cxt + (size_t)rowbase * LATD;
    const float* w1s = g_w1s + w1s_off;

    auto load_tile = [&](int buf, int c) {
        int k0 = c * 32;
        float* A_s  = sm + buf * MLP_BUF;
        float* Bh_s = A_s + 2304;
        float* Bl_s = Bh_s + 8192;
        if (k0 < D) {
#pragma unroll
            for (int it = 0; it < 2; it++) {
                int m = t + 256 * it;
                int r = m >> 3, kq = m & 7;
                cp_async16(&A_s[r * 36 + 4 * kq],
                           &vecs[(size_t)(row0 + r) * D + k0 + 4 * kq]);
            }
        } else {
#pragma unroll
            for (int it = 0; it < 2; it++) {
                int m = t + 256 * it;
                int r = m >> 3, kq = m & 7;
                cp_async16(&A_s[r * 36 + 4 * kq],
                           &cxt[(size_t)(row0 + r) * LATD + 4 * kq]);
            }
        }
        // B planes at 32-float pitch with XOR-f4 swizzle: f4' = f4 ^ (row&7)
        const float* bh = w1s + (size_t)c * 16384;
#pragma unroll
        for (int it = 0; it < 8; it++) {
            int m = t + 256 * it;
            int r = m >> 3, q = m & 7;
            int sq = q ^ (r & 7);
            cp_async16(&Bh_s[r * 32 + 4 * sq], &bh[r * 32 + 4 * q]);
            cp_async16(&Bl_s[r * 32 + 4 * sq], &bh[8192 + r * 32 + 4 * q]);
        }
        cp_commit();
    };

    load_tile(0, 0);
    for (int c = 0; c < NC; c++) {
        if (c + 1 < NC) { load_tile((c + 1) & 1, c + 1); cp_wait<1>(); }
        else            { cp_wait<0>(); }
        __syncthreads();
        const float* A_s  = sm + (c & 1) * MLP_BUF;
        const float* Bh_s = A_s + 2304;
        const float* Bl_s = Bh_s + 8192;
#pragma unroll
        for (int ks = 0; ks < 4; ks++) {
            // A fragments for the warp's 2 row-tiles
            unsigned ah[2][4], al[2][4];
#pragma unroll
            for (int rt = 0; rt < 2; rt++) {
                int ra = wr * 32 + rt * 16 + g;
                float v0 = A_s[ra * 36 + ks * 8 + tq];
                float v1 = A_s[(ra + 8) * 36 + ks * 8 + tq];
                float v2 = A_s[ra * 36 + ks * 8 + tq + 4];
                float v3 = A_s[(ra + 8) * 36 + ks * 8 + tq + 4];
                ah[rt][0] = to_tf32_bits(v0); al[rt][0] = to_tf32_bits(v0 - __uint_as_float(ah[rt][0]));
                ah[rt][1] = to_tf32_bits(v1); al[rt][1] = to_tf32_bits(v1 - __uint_as_float(ah[rt][1]));
                ah[rt][2] = to_tf32_bits(v2); al[rt][2] = to_tf32_bits(v2 - __uint_as_float(ah[rt][2]));
                ah[rt][3] = to_tf32_bits(v3); al[rt][3] = to_tf32_bits(v3 - __uint_as_float(ah[rt][3]));
            }
            // swizzled B float-offsets for this (ks, lane): conflict-free across warp
            int sw0 = (((2 * ks) ^ g) << 2) + tq;
            int sw1 = (((2 * ks + 1) ^ g) << 2) + tq;
#pragma unroll
            for (int nt = 0; nt < 8; nt++) {
                int bbase = (wc * 64 + nt * 8 + g) * 32;
                unsigned bh0 = __float_as_uint(Bh_s[bbase + sw0]);
                unsigned bh1 = __float_as_uint(Bh_s[bbase + sw1]);
                unsigned bl0 = __float_as_uint(Bl_s[bbase + sw0]);
                unsigned bl1 = __float_as_uint(Bl_s[bbase + sw1]);
#pragma unroll
                for (int rt = 0; rt < 2; rt++) {
                    mma_tf32(acc[rt * 8 + nt], ah[rt], bh0, bh1);
                    mma_tf32(acc[rt * 8 + nt], ah[rt], bl0, bl1);
                    mma_tf32(acc[rt * 8 + nt], al[rt], bh0, bh1);
                }
            }
        }
        __syncthreads();
    }

    // epilogue: h = relu(D + b1) from accumulator registers -> h_s
#pragma unroll
    for (int nt = 0; nt < 8; nt++) {
        int col = wc * 64 + nt * 8 + 2 * tq;
        float bA = b1[col], bB = b1[col + 1];
#pragma unroll
        for (int rt = 0; rt < 2; rt++) {
            int row = wr * 32 + rt * 16 + g;
            float* a = acc[rt * 8 + nt];
            h_s[row * HP + col]           = fmaxf(a[0] + bA, 0.f);
            h_s[row * HP + col + 1]       = fmaxf(a[1] + bB, 0.f);
            h_s[(row + 8) * HP + col]     = fmaxf(a[2] + bA, 0.f);
            h_s[(row + 8) * HP + col + 1] = fmaxf(a[3] + bB, 0.f);
        }
    }
    __syncthreads();

    // MLP2: logits = h @ w2^T + b2 (FFMA2)
    for (int p = t; p < 64 * C; p += 256) {
        int r = p / C, cls = p - r * C;
        const ulonglong2* hp = (const ulonglong2*)&h_s[r * HP];
        const ulonglong2* wp = (const ulonglong2*)&w2[(size_t)cls * 256];
        u64 sp2 = 0ull;
#pragma unroll 8
        for (int kq = 0; kq < 64; kq++) {
            ulonglong2 h4 = hp[kq]; ulonglong2 w4 = wp[kq];
            ffma2(sp2, h4.x, w4.x); ffma2(sp2, h4.y, w4.y);
        }
        logit_s[p] = hadd2(sp2) + b2[cls];
    }
    __syncthreads();

    // per-row loss / accuracy
    if (t < 64) {
        int gi = row0 + t;
        int y = labels[gi];
        float loss;
        int corr;
        if (BCE) {
            float z = logit_s[t];
            float sp = (z > 0.f) ? (z + log1pf(__expf(-z))) : log1pf(__expf(z));
            loss = sp - (float)y * z;
            corr = (((z > 0.f) ? 1 : 0) == y) ? 1 : 0;
        } else {
            float mx = logit_s[t * C];
            int am = 0;
#pragma unroll
            for (int c = 1; c < C; c++) {
                float v = logit_s[t * C + c];
                if (v > mx) { mx = v; am = c; }
            }
            float s = 0.f;
#pragma unroll
            for (int c = 0; c < C; c++) s += __expf(logit_s[t * C + c] - mx);
            loss = logf(s) + mx - logit_s[t * C + y];
            corr = (am == y) ? 1 : 0;
        }
        red[t] = loss;
        ((int*)red)[64 + t] = corr;
    }
    __syncthreads();
    if (t < 32) {
        float L = red[t] + red[t + 32];
        int Ck = ((int*)red)[64 + t] + ((int*)red)[64 + t + 32];
#pragma unroll
        for (int o = 16; o > 0; o >>= 1) {
            L += __shfl_xor_sync(0xffffffffu, L, o);
            Ck += __shfl_xor_sync(0xffffffffu, Ck, o);
        }
        if (t == 0) {
            atomicAdd(&g_loss[head], (double)L);
            atomicAdd(&g_corr[head], (unsigned int)Ck);
        }
    }
}

__global__ void finalize_kernel(float* __restrict__ out) {
    if (threadIdx.x == 0 && blockIdx.x == 0) {
        double L = g_loss[0] + g_loss[1] + g_loss[2];
        out[0] = (float)(L / (double)NBATCH);
        out[1] = (float)g_corr[1] / (float)NA;
        out[2] = (float)g_corr[0] / (float)NT;
        out[3] = (float)g_corr[2] / (float)NBD;
    }
}

// ---------------- launch (fork/join stream graph) ----------------
extern "C" void kernel_launch(void* const* d_in, const int* in_sizes, int n_in,
                              void* d_out, int out_size) {
    const float* src        = (const float*)d_in[0];
    const float* topo_vecs  = (const float*)d_in[1];
    const float* atom_vecs  = (const float*)d_in[2];
    const float* bond_vecs  = (const float*)d_in[3];
    const int*   topo_idx   = (const int*)d_in[4];
    const int*   atom_idx   = (const int*)d_in[5];
    const int*   bond_idx   = (const int*)d_in[6];
    const int*   topo_lab   = (const int*)d_in[7];
    const int*   atom_lab   = (const int*)d_in[8];
    const int*   bond_lab   = (const int*)d_in[9];
    const float* A_topo_w   = (const float*)d_in[10];
    const float* A_topo_b   = (const float*)d_in[11];
    const float* A_atom_w   = (const float*)d_in[12];
    const float* A_atom_b   = (const float*)d_in[13];
    const float* A_bond_w   = (const float*)d_in[14];
    const float* A_bond_b   = (const float*)d_in[15];
    const float* topo_w1    = (const float*)d_in[16];
    const float* topo_b1    = (const float*)d_in[17];
    const float* topo_w2    = (const float*)d_in[18];
    const float* topo_b2    = (const float*)d_in[19];
    const float* atom_w1    = (const float*)d_in[20];
    const float* atom_b1    = (const float*)d_in[21];
    const float* atom_w2    = (const float*)d_in[22];
    const float* atom_b2    = (const float*)d_in[23];
    const float* bond_w1    = (const float*)d_in[24];
    const float* bond_b1    = (const float*)d_in[25];
    const float* bond_w2    = (const float*)d_in[26];
    const float* bond_b2    = (const float*)d_in[27];
    float* out = (float*)d_out;

    int attn_smem = (LSRC * SRC_P + LATD * SRCT_P + 64 * LSRC) * (int)sizeof(float);
    int mlp_smem  = MLP_SMEM_FLOATS * (int)sizeof(float);

    static cudaStream_t sA = nullptr, sB = nullptr;
    static cudaEvent_t eRoot, eSort, eAttn, eW, eT, eA2;
    if (!sA) {
        cudaStreamCreateWithFlags(&sA, cudaStreamNonBlocking);
        cudaStreamCreateWithFlags(&sB, cudaStreamNonBlocking);
        cudaEventCreateWithFlags(&eRoot, cudaEventDisableTiming);
        cudaEventCreateWithFlags(&eSort, cudaEventDisableTiming);
        cudaEventCreateWithFlags(&eAttn, cudaEventDisableTiming);
        cudaEventCreateWithFlags(&eW,    cudaEventDisableTiming);
        cudaEventCreateWithFlags(&eT,    cudaEventDisableTiming);
        cudaEventCreateWithFlags(&eA2,   cudaEventDisableTiming);
        cudaFuncSetAttribute(attn_kernel, cudaFuncAttributeMaxDynamicSharedMemorySize, attn_smem);
        cudaFuncSetAttribute(mlp_kernel<512, 1, true>,   cudaFuncAttributeMaxDynamicSharedMemorySize, mlp_smem);
        cudaFuncSetAttribute(mlp_kernel<512, 40, false>, cudaFuncAttributeMaxDynamicSharedMemorySize, mlp_smem);
        cudaFuncSetAttribute(mlp_kernel<768, 4, false>,  cudaFuncAttributeMaxDynamicSharedMemorySize, mlp_smem);
    }

    cudaEventRecord(eRoot, 0);
    cudaStreamWaitEvent(sA, eRoot, 0);
    cudaStreamWaitEvent(sB, eRoot, 0);

    // sort chain on sA
    zero_kernel<<<4, 256, 0, sA>>>();
    hist3_kernel<<<64, 256, 0, sA>>>(topo_idx, atom_idx, bond_idx);
    scan_kernel<<<3, 256, 0, sA>>>();
    scatter3_kernel<<<(NBD + 255) / 256, 256, 0, sA>>>(topo_idx, atom_idx, bond_idx);
    cudaEventRecord(eSort, sA);

    // w1 hi/lo pre-split on sB
    w1split_kernel<<<(17 * 2048 + 255) / 256, 256, 0, sB>>>(topo_w1, 544, 17, 0);
    w1split_kernel<<<(17 * 2048 + 255) / 256, 256, 0, sB>>>(atom_w1, 544, 17, 278528);
    w1split_kernel<<<(25 * 2048 + 255) / 256, 256, 0, sB>>>(bond_w1, 800, 25, 557056);
    cudaEventRecord(eW, sB);

    // qproj on default stream
    qproj_kernel<512><<<NT / 64, 256>>>(topo_vecs, A_topo_w, A_topo_b, 0);
    qproj_kernel<512><<<NA / 64, 256>>>(atom_vecs, A_atom_w, A_atom_b, NT);
    qproj_kernel<768><<<NBD / 64, 256>>>(bond_vecs, A_bond_w, A_bond_b, NT + NA);

    cudaStreamWaitEvent(0, eSort, 0);
    attn_kernel<<<dim3(256, 3), 256, attn_smem>>>(src);
    cudaEventRecord(eAttn, 0);

    // three MLP heads concurrent (need attn + w1 split)
    cudaStreamWaitEvent(sA, eAttn, 0);
    cudaStreamWaitEvent(sA, eW, 0);
    cudaStreamWaitEvent(sB, eAttn, 0);
    cudaStreamWaitEvent(0, eW, 0);
    mlp_kernel<512, 1, true><<<NT / 64, 256, mlp_smem, sA>>>(
        topo_vecs, 0, topo_b1, topo_w2, topo_b2, topo_lab, 0, 0);
    mlp_kernel<512, 40, false><<<NA / 64, 256, mlp_smem, sB>>>(
        atom_vecs, 278528, atom_b1, atom_w2, atom_b2, atom_lab, NT, 1);
    mlp_kernel<768, 4, false><<<NBD / 64, 256, mlp_smem>>>(
        bond_vecs, 557056, bond_b1, bond_w2, bond_b2, bond_lab, NT + NA, 2);
    cudaEventRecord(eT, sA);
    cudaEventRecord(eA2, sB);
    cudaStreamWaitEvent(0, eT, 0);
    cudaStreamWaitEvent(0, eA2, 0);

    finalize_kernel<<<1, 1>>>(out);
}